// round 3
// baseline (speedup 1.0000x reference)
#include <cuda_runtime.h>
#include <math.h>

#define TT   30
#define BB   32
#define VV   32
#define FF   128
#define LL   256
#define LFF  64
#define HH   8
#define DHH  16
#define HISTN 10
#define MROWS (TT*BB*VV)   // 30720

// ---------------- scratch (no allocations allowed) ----------------
__device__ float g_Kproj[BB*LL*FF];     // lane keys   [B,L,F]
__device__ float g_LV[BB*LL*FF];        // logsig(lane values) [B,L,F]
__device__ unsigned char g_mask[BB*LL]; // any-over-HIST mask
__device__ float g_q[MROWS*FF];
__device__ float g_r[MROWS*FF];
__device__ float g_pre[MROWS*FF];       // (r*att) in [T,B,(h,v,d)] layout == raw reshape

// ---------------- lane projection: out[b,l,f] = lanes[b,l,:]·W[f,:] + b[f] ----------------
template<bool LOGSIG>
__global__ __launch_bounds__(256) void lane_proj_kernel(
    const float* __restrict__ lanes, const float* __restrict__ W,
    const float* __restrict__ bias, float* __restrict__ out)
{
    __shared__ float Wsh[LFF][FF + 1];   // transposed, padded
    __shared__ float lsh[32][LFF];
    __shared__ float bsh[FF];
    int tid = threadIdx.x;
    int row0 = blockIdx.x * 32;          // flat (b*L + l) row base

    #pragma unroll
    for (int i = 0; i < 32; i++) {       // 128*64 = 8192 weights
        int idx = tid + i * 256;
        int f = idx >> 6, j = idx & 63;
        Wsh[j][f] = W[idx];
    }
    if (tid < FF) bsh[tid] = bias[tid];
    #pragma unroll
    for (int i = 0; i < 2; i++) {        // 32 rows * 64 floats
        int idx = tid + i * 256;
        int r = idx >> 4;
        int c = (idx & 15) * 4;
        *(float4*)&lsh[r][c] = *(const float4*)(lanes + (size_t)(row0 + r) * LFF + c);
    }
    __syncthreads();

    int f = tid & 127;
    for (int r = tid >> 7; r < 32; r += 2) {
        float acc = bsh[f];
        #pragma unroll
        for (int j = 0; j < LFF; j++) acc += lsh[r][j] * Wsh[j][f];
        if (LOGSIG) {
            acc = (acc >= 0.f) ? -log1pf(expf(-acc)) : acc - log1pf(expf(acc));
        }
        out[(size_t)(row0 + r) * FF + f] = acc;
    }
}

// ---------------- mask: any over HIST, with dtype self-detection ----------------
// The harness may deliver the bool array as uint8 (1B), int32 (4B, values 0/1),
// or float32 (4B, values 0.0/1.0). Classify from the data itself:
//   all 32-bit words in {0,1}          -> int32 bools
//   else all words in {0.0f, 1.0f}     -> float32 bools
//   else                               -> genuine uint8 bools
// Never reads past 81920 bytes unless the 4-byte hypothesis holds (buffer is
// then 327680 bytes). Deterministic for fixed inputs.
__global__ void mask_kernel(const unsigned char* __restrict__ m)
{
    int tid = threadIdx.x;
    const unsigned int* w = (const unsigned int*)m;
    bool okI = true, okF = true;
    for (int j = tid; j < (HISTN * BB * LL) / 4; j += 256) {  // 20480 words = 81920 bytes
        unsigned int x = w[j];
        if (x > 1u) okI = false;
        if (x != 0u && x != 0x3F800000u) okF = false;
    }
    okI = __syncthreads_and((int)okI) != 0;
    okF = __syncthreads_and((int)okF) != 0;
    int cls = okI ? 0 : (okF ? 1 : 2);

    for (int i = tid; i < BB * LL; i += 256) {
        unsigned int any = 0;
        #pragma unroll
        for (int h = 0; h < HISTN; h++) {
            int j = h * BB * LL + i;
            unsigned int v;
            if (cls == 0)      v = w[j];
            else if (cls == 1) v = (w[j] != 0u);
            else               v = m[j];
            any |= v;
        }
        g_mask[i] = any ? 1 : 0;
    }
}

// ---------------- generic 30720x128x128 GEMM: C = A @ W^T + bias (+E1-E2) ----------------
template<bool SUM_AB, bool EPI>
__global__ __launch_bounds__(256) void gemm128_kernel(
    const float* __restrict__ A1, const float* __restrict__ A2,
    const float* __restrict__ W,  const float* __restrict__ bias,
    float* __restrict__ C,
    const float* __restrict__ E1, const float* __restrict__ E2)
{
    __shared__ float Ash[64][36];
    __shared__ float Wsh[32][132];
    int tid = threadIdx.x;
    int tx = tid & 31, ty = tid >> 5;
    int m0 = blockIdx.x * 64;

    float acc[8][4];
    #pragma unroll
    for (int i = 0; i < 8; i++)
        #pragma unroll
        for (int j = 0; j < 4; j++) acc[i][j] = 0.f;

    for (int k0 = 0; k0 < 128; k0 += 32) {
        #pragma unroll
        for (int i = 0; i < 2; i++) {
            int idx = tid + i * 256;
            int row = idx >> 3, c = (idx & 7) * 4;
            float4 a = *(const float4*)(A1 + (size_t)(m0 + row) * FF + k0 + c);
            if (SUM_AB) {
                float4 b = *(const float4*)(A2 + (size_t)(m0 + row) * FF + k0 + c);
                a.x += b.x; a.y += b.y; a.z += b.z; a.w += b.w;
            }
            *(float4*)&Ash[row][c] = a;
        }
        #pragma unroll
        for (int i = 0; i < 16; i++) {
            int idx = tid + i * 256;
            int n = idx >> 5, kk = idx & 31;
            Wsh[kk][n] = W[n * FF + k0 + kk];
        }
        __syncthreads();
        #pragma unroll
        for (int k = 0; k < 32; k++) {
            float4 b4 = *(float4*)&Wsh[k][tx * 4];
            #pragma unroll
            for (int i = 0; i < 8; i++) {
                float a = Ash[ty * 8 + i][k];
                acc[i][0] += a * b4.x; acc[i][1] += a * b4.y;
                acc[i][2] += a * b4.z; acc[i][3] += a * b4.w;
            }
        }
        __syncthreads();
    }

    int n = tx * 4;
    float4 bb = *(const float4*)(bias + n);
    #pragma unroll
    for (int i = 0; i < 8; i++) {
        int m = m0 + ty * 8 + i;
        float4 o;
        o.x = acc[i][0] + bb.x; o.y = acc[i][1] + bb.y;
        o.z = acc[i][2] + bb.z; o.w = acc[i][3] + bb.w;
        if (EPI) {
            float4 e1 = *(const float4*)(E1 + (size_t)m * FF + n);
            float4 e2 = *(const float4*)(E2 + (size_t)m * FF + n);
            o.x += e1.x - e2.x; o.y += e1.y - e2.y;
            o.z += e1.z - e2.z; o.w += e1.w - e2.w;
        }
        *(float4*)(C + (size_t)m * FF + n) = o;
    }
}

// ---------------- attention: per (b,h), K/LV resident, loop over t ----------------
#define TPB 3
__global__ __launch_bounds__(256) void attn_kernel()
{
    __shared__ float sc[16][256];       // scores / unnormalized p, one 16-row v-chunk
    __shared__ float lvsh[256][16];     // logsig(val) for this (b,h)
    __shared__ float qsh[32][16];
    __shared__ float sinv[16];

    int tid = threadIdx.x;
    int bh = blockIdx.x;
    int b = bh >> 3, h = bh & 7;
    int t0 = blockIdx.y * TPB;
    int l = tid;

    // K row for this l in registers
    float kreg[16];
    const float* kp = g_Kproj + ((size_t)(b * LL + l)) * FF + h * DHH;
    #pragma unroll
    for (int i = 0; i < 4; i++) {
        float4 v = *(const float4*)(kp + i * 4);
        kreg[i*4] = v.x; kreg[i*4+1] = v.y; kreg[i*4+2] = v.z; kreg[i*4+3] = v.w;
    }
    const float* lvp = g_LV + ((size_t)(b * LL + l)) * FF + h * DHH;
    #pragma unroll
    for (int i = 0; i < 4; i++)
        *(float4*)&lvsh[l][i * 4] = *(const float4*)(lvp + i * 4);
    bool mon = g_mask[b * LL + l] != 0;

    int warp = tid >> 5, lane = tid & 31;

    for (int t = t0; t < t0 + TPB; t++) {
        __syncthreads();                 // qsh reuse + first-iter lvsh visibility
        #pragma unroll
        for (int i = 0; i < 2; i++) {    // load q tile [32,16]
            int idx = tid + i * 256;
            int v = idx >> 4, d = idx & 15;
            qsh[v][d] = g_q[((size_t)((t * BB + b) * VV + v)) * FF + h * DHH + d];
        }
        __syncthreads();

        #pragma unroll
        for (int vb = 0; vb < 32; vb += 16) {
            // scores: thread l computes column l for 16 v rows
            #pragma unroll
            for (int v = 0; v < 16; v++) {
                float s = 0.f;
                #pragma unroll
                for (int i = 0; i < 16; i++) s += qsh[vb + v][i] * kreg[i];
                sc[v][l] = mon ? (s * 0.25f) : -1e9f;
            }
            __syncthreads();
            // softmax over l: 2 rows per warp
            #pragma unroll
            for (int rr = 0; rr < 2; rr++) {
                int rv = warp + rr * 8;
                float vals[8];
                float mx = -1e30f;
                #pragma unroll
                for (int i = 0; i < 8; i++) {
                    vals[i] = sc[rv][lane + 32 * i];
                    mx = fmaxf(mx, vals[i]);
                }
                #pragma unroll
                for (int o = 16; o > 0; o >>= 1)
                    mx = fmaxf(mx, __shfl_xor_sync(0xffffffffu, mx, o));
                float sm = 0.f;
                #pragma unroll
                for (int i = 0; i < 8; i++) {
                    float p = expf(vals[i] - mx);
                    sc[rv][lane + 32 * i] = p;
                    sm += p;
                }
                #pragma unroll
                for (int o = 16; o > 0; o >>= 1)
                    sm += __shfl_xor_sync(0xffffffffu, sm, o);
                if (lane == 0) sinv[rv] = 1.f / sm;
            }
            __syncthreads();
            // att[v,d] = exp( (1/sum) * sum_l p_un * lv ) ; multiply by r, store reshaped
            {
                int vv = tid >> 4, d = tid & 15;
                float acc = 0.f;
                #pragma unroll 8
                for (int ll2 = 0; ll2 < 256; ll2++) acc += sc[vv][ll2] * lvsh[ll2][d];
                float att = expf(acc * sinv[vv]);
                int vg = vb + vv;
                float rval = g_r[((size_t)((t * BB + b) * VV + vg)) * FF + h * DHH + d];
                g_pre[((size_t)(t * BB + b)) * (VV * FF) + h * (VV * DHH) + vg * DHH + d] = rval * att;
            }
            __syncthreads();
        }
    }
}

// ---------------- launch ----------------
extern "C" void kernel_launch(void* const* d_in, const int* in_sizes, int n_in,
                              void* d_out, int out_size)
{
    const float* vehicles    = (const float*)d_in[0];
    const float* initial_pos = (const float*)d_in[1];
    const float* lanes       = (const float*)d_in[2];
    const unsigned char* mask_lanes = (const unsigned char*)d_in[3];
    const float* Wk = (const float*)d_in[4];
    const float* bk = (const float*)d_in[5];
    const float* Wv = (const float*)d_in[6];
    const float* bv = (const float*)d_in[7];
    const float* Wq = (const float*)d_in[8];
    const float* bq = (const float*)d_in[9];
    const float* Wr = (const float*)d_in[10];
    const float* br = (const float*)d_in[11];
    const float* Wc = (const float*)d_in[12];
    const float* bc = (const float*)d_in[13];
    float* out = (float*)d_out;

    float *gK, *gLV, *gq, *gr, *gpre;
    cudaGetSymbolAddress((void**)&gK,   g_Kproj);
    cudaGetSymbolAddress((void**)&gLV,  g_LV);
    cudaGetSymbolAddress((void**)&gq,   g_q);
    cudaGetSymbolAddress((void**)&gr,   g_r);
    cudaGetSymbolAddress((void**)&gpre, g_pre);

    // 1) lane projections + mask
    lane_proj_kernel<false><<<BB * LL / 32, 256>>>(lanes, Wk, bk, gK);
    lane_proj_kernel<true ><<<BB * LL / 32, 256>>>(lanes, Wv, bv, gLV);
    mask_kernel<<<1, 256>>>(mask_lanes);

    // 2) q, r projections on v = vehicles + initial_pos
    gemm128_kernel<true, false><<<MROWS / 64, 256>>>(vehicles, initial_pos, Wq, bq, gq, nullptr, nullptr);
    gemm128_kernel<true, false><<<MROWS / 64, 256>>>(vehicles, initial_pos, Wr, br, gr, nullptr, nullptr);

    // 3) attention
    attn_kernel<<<dim3(BB * HH, TT / TPB), 256>>>();

    // 4) combine + residual: out = pre @ Wc^T + bc + vehicles - initial_pos
    gemm128_kernel<false, true><<<MROWS / 64, 256>>>(gpre, nullptr, Wc, bc, out, vehicles, initial_pos);
}

// round 4
// speedup vs baseline: 1.0181x; 1.0181x over previous
#include <cuda_runtime.h>
#include <math.h>

#define TT   30
#define BB   32
#define VV   32
#define FF   128
#define LL   256
#define LFF  64
#define HH   8
#define DHH  16
#define HISTN 10
#define MROWS (TT*BB*VV)   // 30720

// ---------------- scratch (no allocations allowed) ----------------
__device__ float g_Kproj[BB*LL*FF];     // lane keys   [B,L,F]
__device__ float g_LV[BB*LL*FF];        // logsig(lane values) [B,L,F]
__device__ unsigned char g_mask[BB*LL]; // any-over-HIST mask
__device__ float g_q[MROWS*FF];
__device__ float g_r[MROWS*FF];
__device__ float g_pre[MROWS*FF];       // (r*att) in [T,B,(h,v,d)] layout == raw reshape

// ---------------- lane projection: out[b,l,f] = lanes[b,l,:]·W[f,:] + b[f] ----------------
template<bool LOGSIG>
__global__ __launch_bounds__(256) void lane_proj_kernel(
    const float* __restrict__ lanes, const float* __restrict__ W,
    const float* __restrict__ bias, float* __restrict__ out)
{
    __shared__ float Wsh[LFF][FF + 1];   // transposed, padded
    __shared__ float lsh[32][LFF];
    __shared__ float bsh[FF];
    int tid = threadIdx.x;
    int row0 = blockIdx.x * 32;          // flat (b*L + l) row base

    #pragma unroll
    for (int i = 0; i < 32; i++) {       // 128*64 = 8192 weights
        int idx = tid + i * 256;
        int f = idx >> 6, j = idx & 63;
        Wsh[j][f] = W[idx];
    }
    if (tid < FF) bsh[tid] = bias[tid];
    #pragma unroll
    for (int i = 0; i < 2; i++) {        // 32 rows * 64 floats
        int idx = tid + i * 256;
        int r = idx >> 4;
        int c = (idx & 15) * 4;
        *(float4*)&lsh[r][c] = *(const float4*)(lanes + (size_t)(row0 + r) * LFF + c);
    }
    __syncthreads();

    int f = tid & 127;
    for (int r = tid >> 7; r < 32; r += 2) {
        float acc = bsh[f];
        #pragma unroll
        for (int j = 0; j < LFF; j++) acc += lsh[r][j] * Wsh[j][f];
        if (LOGSIG) {
            acc = (acc >= 0.f) ? -log1pf(expf(-acc)) : acc - log1pf(expf(acc));
        }
        out[(size_t)(row0 + r) * FF + f] = acc;
    }
}

// ---------------- mask: any over HIST, with dtype self-detection ----------------
__global__ void mask_kernel(const unsigned char* __restrict__ m)
{
    int tid = threadIdx.x;
    const unsigned int* w = (const unsigned int*)m;
    bool okI = true, okF = true;
    for (int j = tid; j < (HISTN * BB * LL) / 4; j += 256) {
        unsigned int x = w[j];
        if (x > 1u) okI = false;
        if (x != 0u && x != 0x3F800000u) okF = false;
    }
    okI = __syncthreads_and((int)okI) != 0;
    okF = __syncthreads_and((int)okF) != 0;
    int cls = okI ? 0 : (okF ? 1 : 2);

    for (int i = tid; i < BB * LL; i += 256) {
        unsigned int any = 0;
        #pragma unroll
        for (int h = 0; h < HISTN; h++) {
            int j = h * BB * LL + i;
            unsigned int v;
            if (cls == 0)      v = w[j];
            else if (cls == 1) v = (w[j] != 0u);
            else               v = m[j];
            any |= v;
        }
        g_mask[i] = any ? 1 : 0;
    }
}

// ---------------- generic 30720x128x128 GEMM: C = A @ W^T + bias (+E1-E2) ----------------
template<bool SUM_AB, bool EPI>
__global__ __launch_bounds__(256) void gemm128_kernel(
    const float* __restrict__ A1, const float* __restrict__ A2,
    const float* __restrict__ W,  const float* __restrict__ bias,
    float* __restrict__ C,
    const float* __restrict__ E1, const float* __restrict__ E2)
{
    __shared__ float Ash[64][36];
    __shared__ float Wsh[32][132];
    int tid = threadIdx.x;
    int tx = tid & 31, ty = tid >> 5;
    int m0 = blockIdx.x * 64;

    float acc[8][4];
    #pragma unroll
    for (int i = 0; i < 8; i++)
        #pragma unroll
        for (int j = 0; j < 4; j++) acc[i][j] = 0.f;

    for (int k0 = 0; k0 < 128; k0 += 32) {
        #pragma unroll
        for (int i = 0; i < 2; i++) {
            int idx = tid + i * 256;
            int row = idx >> 3, c = (idx & 7) * 4;
            float4 a = *(const float4*)(A1 + (size_t)(m0 + row) * FF + k0 + c);
            if (SUM_AB) {
                float4 b = *(const float4*)(A2 + (size_t)(m0 + row) * FF + k0 + c);
                a.x += b.x; a.y += b.y; a.z += b.z; a.w += b.w;
            }
            *(float4*)&Ash[row][c] = a;
        }
        #pragma unroll
        for (int i = 0; i < 16; i++) {
            int idx = tid + i * 256;
            int n = idx >> 5, kk = idx & 31;
            Wsh[kk][n] = W[n * FF + k0 + kk];
        }
        __syncthreads();
        #pragma unroll
        for (int k = 0; k < 32; k++) {
            float4 b4 = *(float4*)&Wsh[k][tx * 4];
            #pragma unroll
            for (int i = 0; i < 8; i++) {
                float a = Ash[ty * 8 + i][k];
                acc[i][0] += a * b4.x; acc[i][1] += a * b4.y;
                acc[i][2] += a * b4.z; acc[i][3] += a * b4.w;
            }
        }
        __syncthreads();
    }

    int n = tx * 4;
    float4 bb = *(const float4*)(bias + n);
    #pragma unroll
    for (int i = 0; i < 8; i++) {
        int m = m0 + ty * 8 + i;
        float4 o;
        o.x = acc[i][0] + bb.x; o.y = acc[i][1] + bb.y;
        o.z = acc[i][2] + bb.z; o.w = acc[i][3] + bb.w;
        if (EPI) {
            float4 e1 = *(const float4*)(E1 + (size_t)m * FF + n);
            float4 e2 = *(const float4*)(E2 + (size_t)m * FF + n);
            o.x += e1.x - e2.x; o.y += e1.y - e2.y;
            o.z += e1.z - e2.z; o.w += e1.w - e2.w;
        }
        *(float4*)(C + (size_t)m * FF + n) = o;
    }
}

// ---------------- fused q+r GEMM: A=(veh+init) loaded once, two weight sets ----------------
__global__ __launch_bounds__(256, 2) void gemm_qr_kernel(
    const float* __restrict__ A1, const float* __restrict__ A2,
    const float* __restrict__ Wq, const float* __restrict__ bq,
    const float* __restrict__ Wr, const float* __restrict__ br,
    float* __restrict__ Cq, float* __restrict__ Cr)
{
    __shared__ float Ash[64][36];
    __shared__ float W1[32][132];
    __shared__ float W2[32][132];
    int tid = threadIdx.x;
    int tx = tid & 31, ty = tid >> 5;
    int m0 = blockIdx.x * 64;

    float accq[8][4], accr[8][4];
    #pragma unroll
    for (int i = 0; i < 8; i++)
        #pragma unroll
        for (int j = 0; j < 4; j++) { accq[i][j] = 0.f; accr[i][j] = 0.f; }

    for (int k0 = 0; k0 < 128; k0 += 32) {
        #pragma unroll
        for (int i = 0; i < 2; i++) {
            int idx = tid + i * 256;
            int row = idx >> 3, c = (idx & 7) * 4;
            float4 a = *(const float4*)(A1 + (size_t)(m0 + row) * FF + k0 + c);
            float4 b = *(const float4*)(A2 + (size_t)(m0 + row) * FF + k0 + c);
            a.x += b.x; a.y += b.y; a.z += b.z; a.w += b.w;
            *(float4*)&Ash[row][c] = a;
        }
        #pragma unroll
        for (int i = 0; i < 16; i++) {
            int idx = tid + i * 256;
            int n = idx >> 5, kk = idx & 31;
            W1[kk][n] = Wq[n * FF + k0 + kk];
            W2[kk][n] = Wr[n * FF + k0 + kk];
        }
        __syncthreads();
        #pragma unroll
        for (int k = 0; k < 32; k++) {
            float4 q4 = *(float4*)&W1[k][tx * 4];
            float4 r4 = *(float4*)&W2[k][tx * 4];
            #pragma unroll
            for (int i = 0; i < 8; i++) {
                float a = Ash[ty * 8 + i][k];
                accq[i][0] += a * q4.x; accq[i][1] += a * q4.y;
                accq[i][2] += a * q4.z; accq[i][3] += a * q4.w;
                accr[i][0] += a * r4.x; accr[i][1] += a * r4.y;
                accr[i][2] += a * r4.z; accr[i][3] += a * r4.w;
            }
        }
        __syncthreads();
    }

    int n = tx * 4;
    float4 bq4 = *(const float4*)(bq + n);
    float4 br4 = *(const float4*)(br + n);
    #pragma unroll
    for (int i = 0; i < 8; i++) {
        int m = m0 + ty * 8 + i;
        float4 oq, orr;
        oq.x  = accq[i][0] + bq4.x; oq.y  = accq[i][1] + bq4.y;
        oq.z  = accq[i][2] + bq4.z; oq.w  = accq[i][3] + bq4.w;
        orr.x = accr[i][0] + br4.x; orr.y = accr[i][1] + br4.y;
        orr.z = accr[i][2] + br4.z; orr.w = accr[i][3] + br4.w;
        *(float4*)(Cq + (size_t)m * FF + n) = oq;
        *(float4*)(Cr + (size_t)m * FF + n) = orr;
    }
}

// ---------------- attention v2: LDS-minimized ----------------
// Per block: one (b,h), TPB2 timesteps. K in registers (thread=l), LV in smem.
// Phase A: scores via float4-broadcast q. Softmax: 4 rows/warp, float4 loads.
// Phase B: thread = (v, d-quad, l-half): 1 scalar LDS + 1 float4 LDS per 8 FMA.
#define TPB2 6
__global__ __launch_bounds__(256) void attn2_kernel()
{
    __shared__ float sc[32][260];       // scores -> unnormalized p (padded rows)
    __shared__ float lvsh[256][16];     // logsig(val) for this (b,h)
    __shared__ float qsh[32][16];
    __shared__ float sinv[32];
    __shared__ float pb[256][4];        // phase-B partials

    int tid = threadIdx.x;
    int b = blockIdx.x >> 3, h = blockIdx.x & 7;
    int t0 = blockIdx.y * TPB2;
    int l = tid;
    int warp = tid >> 5, lane = tid & 31;

    // K row for this l in registers
    float4 k0, k1, k2, k3;
    {
        const float* kp = g_Kproj + ((size_t)(b * LL + l)) * FF + h * DHH;
        k0 = *(const float4*)(kp);
        k1 = *(const float4*)(kp + 4);
        k2 = *(const float4*)(kp + 8);
        k3 = *(const float4*)(kp + 12);
        const float* lvp = g_LV + ((size_t)(b * LL + l)) * FF + h * DHH;
        #pragma unroll
        for (int i = 0; i < 4; i++)
            *(float4*)&lvsh[l][i * 4] = *(const float4*)(lvp + i * 4);
    }
    bool mon = g_mask[b * LL + l] != 0;

    // phase-B thread mapping
    int dq = tid & 3;            // d quad
    int half = (tid >> 2) & 1;   // l parity
    int vB = tid >> 3;           // v row 0..31

    for (int t = t0; t < t0 + TPB2; t++) {
        __syncthreads();                 // protect qsh/sc/sinv reuse
        if (tid < 128) {                 // load q tile [32,16] as float4
            int v = tid >> 2, q4 = tid & 3;
            *(float4*)&qsh[v][q4 * 4] =
                *(const float4*)(g_q + ((size_t)((t * BB + b) * VV + v)) * FF + h * DHH + q4 * 4);
        }
        __syncthreads();

        // ---- Phase A: scores, thread l computes column l for all 32 v ----
        #pragma unroll
        for (int v = 0; v < 32; v++) {
            float4 q0 = *(float4*)&qsh[v][0];
            float4 q1 = *(float4*)&qsh[v][4];
            float4 q2 = *(float4*)&qsh[v][8];
            float4 q3 = *(float4*)&qsh[v][12];
            float s = q0.x * k0.x + q0.y * k0.y + q0.z * k0.z + q0.w * k0.w
                    + q1.x * k1.x + q1.y * k1.y + q1.z * k1.z + q1.w * k1.w
                    + q2.x * k2.x + q2.y * k2.y + q2.z * k2.z + q2.w * k2.w
                    + q3.x * k3.x + q3.y * k3.y + q3.z * k3.z + q3.w * k3.w;
            sc[v][l] = mon ? (s * 0.25f) : -1e9f;
        }
        __syncthreads();

        // ---- softmax over l (rows = v): warp handles rows warp, warp+8, +16, +24 ----
        #pragma unroll
        for (int rr = 0; rr < 4; rr++) {
            int rv = warp + rr * 8;
            float4 a = *(float4*)&sc[rv][lane * 8];
            float4 c = *(float4*)&sc[rv][lane * 8 + 4];
            float mx = fmaxf(fmaxf(fmaxf(a.x, a.y), fmaxf(a.z, a.w)),
                             fmaxf(fmaxf(c.x, c.y), fmaxf(c.z, c.w)));
            #pragma unroll
            for (int o = 16; o > 0; o >>= 1)
                mx = fmaxf(mx, __shfl_xor_sync(0xffffffffu, mx, o));
            a.x = expf(a.x - mx); a.y = expf(a.y - mx);
            a.z = expf(a.z - mx); a.w = expf(a.w - mx);
            c.x = expf(c.x - mx); c.y = expf(c.y - mx);
            c.z = expf(c.z - mx); c.w = expf(c.w - mx);
            float sm = a.x + a.y + a.z + a.w + c.x + c.y + c.z + c.w;
            #pragma unroll
            for (int o = 16; o > 0; o >>= 1)
                sm += __shfl_xor_sync(0xffffffffu, sm, o);
            *(float4*)&sc[rv][lane * 8] = a;
            *(float4*)&sc[rv][lane * 8 + 4] = c;
            if (lane == 0) sinv[rv] = 1.f / sm;
        }
        __syncthreads();

        // ---- Phase B: acc[d4] = sum over half the l's of p * lv ----
        {
            float4 acc = make_float4(0.f, 0.f, 0.f, 0.f);
            #pragma unroll 4
            for (int j = 0; j < 128; j++) {
                int ll2 = 2 * j + half;
                float p = sc[vB][ll2];
                float4 lv = *(float4*)&lvsh[ll2][dq * 4];
                acc.x += p * lv.x; acc.y += p * lv.y;
                acc.z += p * lv.z; acc.w += p * lv.w;
            }
            *(float4*)&pb[tid][0] = acc;
            __syncthreads();
            if (half == 0) {
                float4 o = *(float4*)&pb[tid ^ 4][0];
                o.x += acc.x; o.y += acc.y; o.z += acc.z; o.w += acc.w;
                float si = sinv[vB];
                float4 r4 = *(const float4*)(g_r + ((size_t)((t * BB + b) * VV + vB)) * FF + h * DHH + dq * 4);
                float4 res;
                res.x = r4.x * expf(o.x * si);
                res.y = r4.y * expf(o.y * si);
                res.z = r4.z * expf(o.z * si);
                res.w = r4.w * expf(o.w * si);
                *(float4*)(g_pre + ((size_t)(t * BB + b)) * (VV * FF)
                           + h * (VV * DHH) + vB * DHH + dq * 4) = res;
            }
        }
    }
}

// ---------------- launch ----------------
extern "C" void kernel_launch(void* const* d_in, const int* in_sizes, int n_in,
                              void* d_out, int out_size)
{
    const float* vehicles    = (const float*)d_in[0];
    const float* initial_pos = (const float*)d_in[1];
    const float* lanes       = (const float*)d_in[2];
    const unsigned char* mask_lanes = (const unsigned char*)d_in[3];
    const float* Wk = (const float*)d_in[4];
    const float* bk = (const float*)d_in[5];
    const float* Wv = (const float*)d_in[6];
    const float* bv = (const float*)d_in[7];
    const float* Wq = (const float*)d_in[8];
    const float* bq = (const float*)d_in[9];
    const float* Wr = (const float*)d_in[10];
    const float* br = (const float*)d_in[11];
    const float* Wc = (const float*)d_in[12];
    const float* bc = (const float*)d_in[13];
    float* out = (float*)d_out;

    float *gK, *gLV, *gq, *gr, *gpre;
    cudaGetSymbolAddress((void**)&gK,   g_Kproj);
    cudaGetSymbolAddress((void**)&gLV,  g_LV);
    cudaGetSymbolAddress((void**)&gq,   g_q);
    cudaGetSymbolAddress((void**)&gr,   g_r);
    cudaGetSymbolAddress((void**)&gpre, g_pre);

    // 1) lane projections + mask
    lane_proj_kernel<false><<<BB * LL / 32, 256>>>(lanes, Wk, bk, gK);
    lane_proj_kernel<true ><<<BB * LL / 32, 256>>>(lanes, Wv, bv, gLV);
    mask_kernel<<<1, 256>>>(mask_lanes);

    // 2) fused q, r projections on v = vehicles + initial_pos
    gemm_qr_kernel<<<MROWS / 64, 256>>>(vehicles, initial_pos, Wq, bq, Wr, br, gq, gr);

    // 3) attention
    attn2_kernel<<<dim3(BB * HH, TT / TPB2), 256>>>();

    // 4) combine + residual: out = pre @ Wc^T + bc + vehicles - initial_pos
    gemm128_kernel<false, true><<<MROWS / 64, 256>>>(gpre, nullptr, Wc, bc, out, vehicles, initial_pos);
}